// round 12
// baseline (speedup 1.0000x reference)
#include <cuda_runtime.h>
#include <cuda_bf16.h>
#include <mma.h>
#include <math.h>
#include <cstdint>

using namespace nvcuda;

#define NN   10000
#define NE   320000
#define BB   8
#define TTI  12
#define CIN  2
#define HH   64
#define NBT  (NN*BB*TTI)       /* 960000 positions */
#define TOT  (NBT*HH)          /* 61,440,000 floats */
#define F4   (BB*TTI*HH/4)     /* 1536 */

// ---------------- scratch (device globals; zero-init at load) ----------------
__device__ __align__(16) float g_T0[TOT];
__device__ __align__(16) float g_Y1[TOT];
__device__ __align__(16) float g_Y2[TOT];
__device__ __align__(16) __nv_bfloat16 g_Sh[TOT];
__device__ __align__(16) __nv_bfloat16 g_Sl[TOT];
__device__ float g_degw[NN];
__device__ int   g_cnt[NN];
__device__ float g_dis[NN];
__device__ int   g_rowptr[NN+1];
__device__ int   g_cursor[NN];
__device__ int   g_colidx[NE];
__device__ float g_ew[NE];
// precomputed bf16 hi/lo weights
__device__ __align__(16) __nv_bfloat16 g_cBh[192*64];    // combine folded B
__device__ __align__(16) __nv_bfloat16 g_cBl[192*64];
__device__ __align__(16) __nv_bfloat16 g_t2Bh[192*192];  // tconv2 B: row j=k*64+c, col m*64+o
__device__ __align__(16) __nv_bfloat16 g_t2Bl[192*192];

__device__ __forceinline__ void bsplit(float v, __nv_bfloat16& h, __nv_bfloat16& l) {
    h = __float2bfloat16(v);
    l = __float2bfloat16(v - __bfloat162float(h));
}

// ---------------- prep: tconv1 + degree hist + weight hi/lo precompute -------
#define T1_BLOCKS  (NBT/4)      /* 240000 */
#define HIST_BLOCKS (NE/256)    /* 1250 */
#define WPRE_BLOCKS 192         /* 12288 + 36864 = 49152 elements */
__global__ __launch_bounds__(256) void prep_kernel(const float* __restrict__ X,
        const float* __restrict__ w1, const float* __restrict__ b1,
        const float* __restrict__ w2, const float* __restrict__ b2,
        const float* __restrict__ w3, const float* __restrict__ b3,
        const int* __restrict__ row, const float* __restrict__ ew,
        const float* __restrict__ cW,
        const float* __restrict__ t2w1, const float* __restrict__ t2w2,
        const float* __restrict__ t2w3) {
    if (blockIdx.x >= T1_BLOCKS + HIST_BLOCKS) {
        int idx = (int)(blockIdx.x - T1_BLOCKS - HIST_BLOCKS)*256 + threadIdx.x;
        if (idx < 12288) {
            // combine fold: B[(m*64+i)][h], m0 = W0-W2, m1 = W1, m2 = 2*W2
            int j = idx >> 6, h = idx & 63;
            int m = j >> 6, i = j & 63;
            float v;
            if (m == 0)      v = cW[i*64 + h] - cW[8192 + i*64 + h];
            else if (m == 1) v = cW[4096 + i*64 + h];
            else             v = 2.f * cW[8192 + i*64 + h];
            bsplit(v, g_cBh[idx], g_cBl[idx]);
        } else {
            int u = idx - 12288;             // [0, 36864)
            int j = u / 192, col = u - j*192;
            int k = j >> 6, c = j & 63;
            int m = col >> 6, o = col & 63;
            const float* w = (m == 0) ? t2w1 : ((m == 1) ? t2w2 : t2w3);
            bsplit(w[o*192 + c*3 + k], g_t2Bh[u], g_t2Bl[u]);
        }
        return;
    }
    if (blockIdx.x >= T1_BLOCKS) {
        int e = (int)(blockIdx.x - T1_BLOCKS)*256 + threadIdx.x;
        if (e < NE) {
            int r = row[e];
            atomicAdd(&g_degw[r], ew[e]);
            atomicAdd(&g_cnt[r], 1);
        }
        return;
    }
    __shared__ float sw[3][HH*CIN*3];
    __shared__ float sb[3][HH];
    int tid = threadIdx.x;
    for (int i = tid; i < HH*CIN*3; i += 256) { sw[0][i]=w1[i]; sw[1][i]=w2[i]; sw[2][i]=w3[i]; }
    if (tid < HH) { sb[0][tid]=b1[tid]; sb[1][tid]=b2[tid]; sb[2][tid]=b3[tid]; }
    __syncthreads();

    int h  = tid & 63;
    int py = tid >> 6;
    int pos = blockIdx.x*4 + py;                 // pos = (n*B + b)*T + t
    int t  = pos % TTI;
    int nb = pos / TTI;
    int b  = nb % BB;
    int n  = nb / BB;

    float xv[3][CIN];
#pragma unroll
    for (int k = 0; k < 3; k++) {
        int t2 = t + k - 1;
        if (t2 >= 0 && t2 < TTI) {
#pragma unroll
            for (int c = 0; c < CIN; c++)
                xv[k][c] = X[((b*TTI + t2)*NN + n)*CIN + c];
        } else {
            xv[k][0] = 0.f; xv[k][1] = 0.f;
        }
    }
    float p = sb[0][h], q = sb[1][h], r = sb[2][h];
#pragma unroll
    for (int c = 0; c < CIN; c++)
#pragma unroll
        for (int k = 0; k < 3; k++) {
            float v = xv[k][c];
            p += v * sw[0][h*6 + c*3 + k];
            q += v * sw[1][h*6 + c*3 + k];
            r += v * sw[2][h*6 + c*3 + k];
        }
    float sg = 1.f / (1.f + expf(-q));
    g_T0[pos*HH + h] = fmaxf(p*sg + r, 0.f);
}

// single-block exclusive scan of g_cnt -> g_rowptr, g_cursor; also g_dis
__global__ void scan_kernel() {
    __shared__ int s[1024];
    int tid = threadIdx.x;
    int lo = tid * 10;
    int sum = 0;
    for (int r = lo; r < lo+10 && r < NN; r++) {
        sum += g_cnt[r];
        float d = g_degw[r];
        g_dis[r] = d > 0.f ? rsqrtf(d) : 0.f;
    }
    s[tid] = sum;
    __syncthreads();
    for (int off = 1; off < 1024; off <<= 1) {
        int v = (tid >= off) ? s[tid-off] : 0;
        __syncthreads();
        s[tid] += v;
        __syncthreads();
    }
    int run = s[tid] - sum;   // exclusive prefix
    for (int r = lo; r < lo+10 && r < NN; r++) {
        g_rowptr[r] = run;
        g_cursor[r] = run;
        run += g_cnt[r];
    }
    if (tid == 1023) g_rowptr[NN] = s[1023];
}

__global__ void scatter_kernel(const int* __restrict__ row, const int* __restrict__ col,
                               const float* __restrict__ ew) {
    int e = blockIdx.x*256 + threadIdx.x;
    if (e < NE) {
        int r = row[e], c = col[e];
        int p = atomicAdd(&g_cursor[r], 1);
        g_colidx[p] = c;
        g_ew[p] = -g_dis[r] * ew[e] * g_dis[c];   // L_hat weight (sym norm, lambda_max=2)
    }
}

// ---------------- graph prop: y[n,:] = sum_e w[e] * x[col[e],:] ----------------
__global__ __launch_bounds__(256) void prop_kernel(int mode) {
    const float4* __restrict__ x = (const float4*)(mode ? g_Y1 : g_T0);
    float4* __restrict__ y       = (float4*)(mode ? g_Y2 : g_Y1);
    int n = blockIdx.x;
    int f = blockIdx.y*256 + threadIdx.x;     // float4 index in [0,1536)
    int beg = g_rowptr[n], end = g_rowptr[n+1];
    float4 acc = make_float4(0.f, 0.f, 0.f, 0.f);
    int e = beg;
    for (; e + 4 <= end; e += 4) {
        int   c0 = g_colidx[e],   c1 = g_colidx[e+1], c2 = g_colidx[e+2], c3 = g_colidx[e+3];
        float w0 = g_ew[e],       w1 = g_ew[e+1],     w2 = g_ew[e+2],     w3 = g_ew[e+3];
        float4 v0 = x[c0*F4 + f], v1 = x[c1*F4 + f],  v2 = x[c2*F4 + f],  v3 = x[c3*F4 + f];
        acc.x += w0*v0.x + w1*v1.x + w2*v2.x + w3*v3.x;
        acc.y += w0*v0.y + w1*v1.y + w2*v2.y + w3*v3.y;
        acc.z += w0*v0.z + w1*v1.z + w2*v2.z + w3*v3.z;
        acc.w += w0*v0.w + w1*v1.w + w2*v2.w + w3*v3.w;
    }
    for (; e < end; e++) {
        int c = g_colidx[e]; float w = g_ew[e];
        float4 v = x[c*F4 + f];
        acc.x += w*v.x; acc.y += w*v.y; acc.z += w*v.z; acc.w += w*v.w;
    }
    y[n*F4 + f] = acc;
}

// ---------------- cheb combine via WMMA bf16 hi/lo ---------------------------
// Per CTA: 128 positions. acc = Ah*Bh + Al*Bh + Ah*Bl, A=[T0|Y1|Y2] (hi|lo),
// B = folded weights (precomputed bf16 hi/lo). Output -> g_Sh/g_Sl (bf16 hi/lo).
#define CMB_A_ST   392                      /* elements; mult of 8 */
#define CMB_A_B    (128*CMB_A_ST*2)         /* 100352 */
#define CMB_BH_OFF CMB_A_B
#define CMB_B_ST   72
#define CMB_B_B    (192*CMB_B_ST*2)         /* 27648 */
#define CMB_BL_OFF (CMB_BH_OFF + CMB_B_B)   /* 128000 */
#define CMB_BIAS_OFF (CMB_BL_OFF + CMB_B_B) /* 155648 */
#define CMB_SMEM   (CMB_BIAS_OFF + 256)     /* 155904 */
__global__ __launch_bounds__(256, 1) void combine_kernel(const float* __restrict__ bias) {
    extern __shared__ char smc[];
    __nv_bfloat16* As = (__nv_bfloat16*)smc;
    int tid = threadIdx.x;
    int base = blockIdx.x * 128 * 64;

    // stage A' (fp32 -> bf16 hi/lo), cols: m*64+i (hi), 192+m*64+i (lo)
    for (int u = tid; u < 128*48; u += 256) {
        int p = u / 48, q = u - p*48;
        int m = q >> 4, i0 = (q & 15) * 4;
        const float* src = (m == 0) ? g_T0 : ((m == 1) ? g_Y1 : g_Y2);
        float4 v = *(const float4*)&src[base + p*64 + i0];
        __nv_bfloat16 h0,h1,h2,h3,l0,l1,l2,l3;
        bsplit(v.x,h0,l0); bsplit(v.y,h1,l1); bsplit(v.z,h2,l2); bsplit(v.w,h3,l3);
        __nv_bfloat16* ar = As + p*CMB_A_ST + m*64 + i0;
        ar[0]=h0; ar[1]=h1; ar[2]=h2; ar[3]=h3;
        ar[192+0]=l0; ar[192+1]=l1; ar[192+2]=l2; ar[192+3]=l3;
    }
    // stage B hi/lo (compact [192][64] -> [192][72])
    {
        __nv_bfloat162* bh = (__nv_bfloat162*)(smc + CMB_BH_OFF);
        __nv_bfloat162* bl = (__nv_bfloat162*)(smc + CMB_BL_OFF);
        const __nv_bfloat162* gh = (const __nv_bfloat162*)g_cBh;
        const __nv_bfloat162* gl = (const __nv_bfloat162*)g_cBl;
        for (int u = tid; u < 192*32; u += 256) {
            int r = u >> 5, c2 = u & 31;
            bh[r*36 + c2] = gh[u];
            bl[r*36 + c2] = gl[u];
        }
    }
    float* bsm = (float*)(smc + CMB_BIAS_OFF);
    if (tid < 64) bsm[tid] = bias[tid];
    __syncthreads();

    int w = tid >> 5;                       // warp = row-tile (8 x 16 rows)
    wmma::fragment<wmma::accumulator,16,16,16,float> acc[4];
#pragma unroll
    for (int ct = 0; ct < 4; ct++) wmma::fill_fragment(acc[ct], 0.f);
    const __nv_bfloat16* Ab = As + w*16*CMB_A_ST;
#pragma unroll
    for (int pass = 0; pass < 3; pass++) {
        const __nv_bfloat16* Bb = (const __nv_bfloat16*)(smc + (pass == 2 ? CMB_BL_OFF : CMB_BH_OFF));
        int aoff = (pass == 1) ? 192 : 0;
        for (int ks = 0; ks < 12; ks++) {
            wmma::fragment<wmma::matrix_a,16,16,16,__nv_bfloat16,wmma::row_major> af;
            wmma::load_matrix_sync(af, Ab + aoff + ks*16, CMB_A_ST);
#pragma unroll
            for (int ct = 0; ct < 4; ct++) {
                wmma::fragment<wmma::matrix_b,16,16,16,__nv_bfloat16,wmma::row_major> bf;
                wmma::load_matrix_sync(bf, Bb + (ks*16)*CMB_B_ST + ct*16, CMB_B_ST);
                wmma::mma_sync(acc[ct], af, bf, acc[ct]);
            }
        }
    }
    __syncthreads();                        // all reads of A/B done
    float* osm = (float*)smc;               // [128][68]
#pragma unroll
    for (int ct = 0; ct < 4; ct++)
        wmma::store_matrix_sync(osm + w*16*68 + ct*16, acc[ct], 68, wmma::mem_row_major);
    __syncthreads();

    for (int u = tid; u < 128*64; u += 256) {
        int p = u >> 6, h = u & 63;
        float v = fmaxf(osm[p*68 + h] + bsm[h], 0.f);
        __nv_bfloat16 hh, ll;
        bsplit(v, hh, ll);
        g_Sh[base + p*64 + h] = hh;
        g_Sl[base + p*64 + h] = ll;
    }
}

// ---------------- temporal conv 2 via WMMA bf16 hi/lo ------------------------
// Per CTA: 8 nb strips = 96 positions. A'[96][384]: col j=k*64+c (hi), 192+j (lo)
// from g_Sh/g_Sl with taps; B[192][192] (cols m*64+o) hi/lo precomputed.
// Single B buffer staged twice (Bh passes 0-1, then Bl pass 2) -> 149 KB smem.
// Epilogue: P*sigmoid(Q)+R, relu, write out[B,T,N,H].
#define T2_NB     8
#define T2_A_ST   392
#define T2_A_B    (96*T2_A_ST*2)            /* 75264 */
#define T2_B_OFF  T2_A_B
#define T2_B_ST   200
#define T2_B_B    (192*T2_B_ST*2)           /* 76800 */
#define T2_BIAS_OFF (T2_B_OFF + T2_B_B)     /* 152064 */
#define T2_SMEM   (T2_BIAS_OFF + 768)       /* 152832 */
__global__ __launch_bounds__(192, 1) void tconv2_kernel(
        const float* __restrict__ b1, const float* __restrict__ b2,
        const float* __restrict__ b3, float* __restrict__ out) {
    extern __shared__ char smc[];
    __nv_bfloat16* As = (__nv_bfloat16*)smc;
    int tid = threadIdx.x;
    int nb0 = blockIdx.x * T2_NB;

    // stage A' from g_Sh/g_Sl with temporal taps (zero halo)
    {
        const __nv_bfloat162* gh = (const __nv_bfloat162*)g_Sh;
        const __nv_bfloat162* gl = (const __nv_bfloat162*)g_Sl;
        __nv_bfloat162 zz; zz.x = __float2bfloat16(0.f); zz.y = zz.x;
        for (int u = tid; u < 8*3*12*32; u += 192) {
            int c2 = u & 31; int rest = u >> 5;
            int t = rest % 12; rest /= 12;
            int k = rest % 3;  int strip = rest / 3;
            int tt = t + k - 1;
            __nv_bfloat162 vh = zz, vl = zz;
            if (tt >= 0 && tt < 12) {
                int gi = ((nb0 + strip)*768 + tt*64)/2 + c2;
                vh = gh[gi]; vl = gl[gi];
            }
            int p = strip*12 + t;
            __nv_bfloat162* ar = (__nv_bfloat162*)(As + p*T2_A_ST + k*64) + c2;
            ar[0] = vh;
            ar[96] = vl;                    // +192 elements = +96 bf162
        }
    }
    // stage Bh (compact [192][192] -> [192][200])
    {
        __nv_bfloat162* bh = (__nv_bfloat162*)(smc + T2_B_OFF);
        const __nv_bfloat162* gh = (const __nv_bfloat162*)g_t2Bh;
        for (int u = tid; u < 192*96; u += 192) {
            int r = u / 96, c2 = u - r*96;
            bh[r*100 + c2] = gh[u];
        }
    }
    float* bsm = (float*)(smc + T2_BIAS_OFF);
    if (tid < 192) {
        int m = tid >> 6, o = tid & 63;
        bsm[tid] = (m == 0) ? b1[o] : ((m == 1) ? b2[o] : b3[o]);
    }
    __syncthreads();

    int w = tid >> 5;                       // warp = row-tile (6 x 16 rows)
    wmma::fragment<wmma::accumulator,16,16,16,float> acc[12];
#pragma unroll
    for (int ct = 0; ct < 12; ct++) wmma::fill_fragment(acc[ct], 0.f);
    const __nv_bfloat16* Ab = As + w*16*T2_A_ST;
    const __nv_bfloat16* Bb = (const __nv_bfloat16*)(smc + T2_B_OFF);

    // passes 0 (Ah*Bh) and 1 (Al*Bh)
#pragma unroll
    for (int pass = 0; pass < 2; pass++) {
        int aoff = (pass == 1) ? 192 : 0;
        for (int ks = 0; ks < 12; ks++) {
            wmma::fragment<wmma::matrix_a,16,16,16,__nv_bfloat16,wmma::row_major> af;
            wmma::load_matrix_sync(af, Ab + aoff + ks*16, T2_A_ST);
#pragma unroll
            for (int ct = 0; ct < 12; ct++) {
                wmma::fragment<wmma::matrix_b,16,16,16,__nv_bfloat16,wmma::row_major> bf;
                wmma::load_matrix_sync(bf, Bb + (ks*16)*T2_B_ST + ct*16, T2_B_ST);
                wmma::mma_sync(acc[ct], af, bf, acc[ct]);
            }
        }
    }
    __syncthreads();
    // restage Bl over the same buffer
    {
        __nv_bfloat162* bl = (__nv_bfloat162*)(smc + T2_B_OFF);
        const __nv_bfloat162* gl = (const __nv_bfloat162*)g_t2Bl;
        for (int u = tid; u < 192*96; u += 192) {
            int r = u / 96, c2 = u - r*96;
            bl[r*100 + c2] = gl[u];
        }
    }
    __syncthreads();
    // pass 2 (Ah*Bl)
    for (int ks = 0; ks < 12; ks++) {
        wmma::fragment<wmma::matrix_a,16,16,16,__nv_bfloat16,wmma::row_major> af;
        wmma::load_matrix_sync(af, Ab + ks*16, T2_A_ST);
#pragma unroll
        for (int ct = 0; ct < 12; ct++) {
            wmma::fragment<wmma::matrix_b,16,16,16,__nv_bfloat16,wmma::row_major> bf;
            wmma::load_matrix_sync(bf, Bb + (ks*16)*T2_B_ST + ct*16, T2_B_ST);
            wmma::mma_sync(acc[ct], af, bf, acc[ct]);
        }
    }
    __syncthreads();
    float* osm = (float*)smc;               // [96][200] (reuses A + part of B)
#pragma unroll
    for (int ct = 0; ct < 12; ct++)
        wmma::store_matrix_sync(osm + w*16*200 + ct*16, acc[ct], 200, wmma::mem_row_major);
    __syncthreads();

    for (int u = tid; u < 96*64; u += 192) {
        int p = u >> 6, o = u & 63;
        float P = osm[p*200 + o]       + bsm[o];
        float Q = osm[p*200 + 64 + o]  + bsm[64 + o];
        float R = osm[p*200 + 128 + o] + bsm[128 + o];
        int strip = p / 12, t = p - strip*12;
        int nb = nb0 + strip; int n = nb >> 3; int b = nb & 7;
        out[((b*TTI + t)*NN + n)*64 + o] = fmaxf(P / (1.f + expf(-Q)) + R, 0.f);
    }
}

// zero the accumulated histograms for the NEXT call (globals are zero at load)
__global__ void cleanup_kernel() {
    int i = blockIdx.x*256 + threadIdx.x;
    if (i < NN) { g_degw[i] = 0.f; g_cnt[i] = 0; }
}

// ---------------- launch ----------------
extern "C" void kernel_launch(void* const* d_in, const int* in_sizes, int n_in,
                              void* d_out, int out_size) {
    const float* X    = (const float*)d_in[0];
    const int*   ei   = (const int*)  d_in[1];
    const float* ew   = (const float*)d_in[2];
    const float* t1w1 = (const float*)d_in[3];  const float* t1b1 = (const float*)d_in[4];
    const float* t1w2 = (const float*)d_in[5];  const float* t1b2 = (const float*)d_in[6];
    const float* t1w3 = (const float*)d_in[7];  const float* t1b3 = (const float*)d_in[8];
    const float* cW   = (const float*)d_in[9];  const float* cb   = (const float*)d_in[10];
    const float* t2w1 = (const float*)d_in[11]; const float* t2b1 = (const float*)d_in[12];
    const float* t2w2 = (const float*)d_in[13]; const float* t2b2 = (const float*)d_in[14];
    const float* t2w3 = (const float*)d_in[15]; const float* t2b3 = (const float*)d_in[16];
    float* out = (float*)d_out;
    const int* row = ei;
    const int* col = ei + NE;

    cudaFuncSetAttribute(combine_kernel, cudaFuncAttributeMaxDynamicSharedMemorySize,
                         CMB_SMEM);
    cudaFuncSetAttribute(tconv2_kernel, cudaFuncAttributeMaxDynamicSharedMemorySize,
                         T2_SMEM);

    prep_kernel   <<<T1_BLOCKS + HIST_BLOCKS + WPRE_BLOCKS, 256>>>(
        X, t1w1,t1b1, t1w2,t1b2, t1w3,t1b3, row, ew, cW, t2w1, t2w2, t2w3);
    scan_kernel   <<<1, 1024>>>();
    scatter_kernel<<<(NE+255)/256, 256>>>(row, col, ew);

    prop_kernel   <<<dim3(NN, 6), 256>>>(0);   // Y1 = L * T0
    prop_kernel   <<<dim3(NN, 6), 256>>>(1);   // Y2 = L * Y1

    combine_kernel<<<NBT/128, 256, CMB_SMEM>>>(cb);   // ncu -s 5 lands here

    tconv2_kernel <<<NN*BB/T2_NB, 192, T2_SMEM>>>(t2b1, t2b2, t2b3, out);

    cleanup_kernel<<<(NN+255)/256, 256>>>();
}

// round 13
// speedup vs baseline: 1.1061x; 1.1061x over previous
#include <cuda_runtime.h>
#include <math.h>

#define NN   10000
#define NE   320000
#define BB   8
#define TTI  12
#define CIN  2
#define HH   64
#define NBT  (NN*BB*TTI)       /* 960000 positions */
#define TOT  (NBT*HH)          /* 61,440,000 floats */
#define F4   (BB*TTI*HH/4)     /* 1536 */

typedef unsigned long long ull;

// ---------------- f32x2 packed-FMA helpers ----------------
__device__ __forceinline__ ull pack2(float a, float b) {
    ull r;
    asm("mov.b64 %0, {%1, %2};" : "=l"(r) : "f"(a), "f"(b));
    return r;
}
__device__ __forceinline__ void unpack2(float& lo, float& hi, ull v) {
    asm("mov.b64 {%0, %1}, %2;" : "=f"(lo), "=f"(hi) : "l"(v));
}
__device__ __forceinline__ void fma2(ull& d, ull a, ull b) {
    asm("fma.rn.f32x2 %0, %1, %2, %0;" : "+l"(d) : "l"(a), "l"(b));
}

// ---------------- scratch (device globals; zero-init at load) ----------------
__device__ __align__(16) float g_T0[TOT];
__device__ __align__(16) float g_Y1[TOT];
__device__ __align__(16) float g_Y2[TOT];
__device__ __align__(16) float g_S [TOT];
__device__ float g_degw[NN];    /* zeroed by cleanup_kernel at end of each call */
__device__ int   g_cnt[NN];     /* ditto */
__device__ float g_dis[NN];
__device__ int   g_rowptr[NN+1];
__device__ int   g_cursor[NN];
__device__ int   g_colidx[NE];
__device__ float g_ew[NE];

// ---------------- hist: degree histogram ----------------
__global__ __launch_bounds__(256) void hist_kernel(const int* __restrict__ row,
                                                   const float* __restrict__ ew) {
    int e = blockIdx.x*256 + threadIdx.x;
    if (e < NE) {
        int r = row[e];
        atomicAdd(&g_degw[r], ew[e]);
        atomicAdd(&g_cnt[r], 1);
    }
}

// single-block exclusive scan of g_cnt -> g_rowptr, g_cursor; also g_dis
__global__ void scan_kernel() {
    __shared__ int s[1024];
    int tid = threadIdx.x;
    int lo = tid * 10;
    int sum = 0;
    for (int r = lo; r < lo+10 && r < NN; r++) {
        sum += g_cnt[r];
        float d = g_degw[r];
        g_dis[r] = d > 0.f ? rsqrtf(d) : 0.f;
    }
    s[tid] = sum;
    __syncthreads();
    for (int off = 1; off < 1024; off <<= 1) {
        int v = (tid >= off) ? s[tid-off] : 0;
        __syncthreads();
        s[tid] += v;
        __syncthreads();
    }
    int run = s[tid] - sum;   // exclusive prefix
    for (int r = lo; r < lo+10 && r < NN; r++) {
        g_rowptr[r] = run;
        g_cursor[r] = run;
        run += g_cnt[r];
    }
    if (tid == 1023) g_rowptr[NN] = s[1023];
}

__global__ void scatter_kernel(const int* __restrict__ row, const int* __restrict__ col,
                               const float* __restrict__ ew) {
    int e = blockIdx.x*256 + threadIdx.x;
    if (e < NE) {
        int r = row[e], c = col[e];
        int p = atomicAdd(&g_cursor[r], 1);
        g_colidx[p] = c;
        g_ew[p] = -g_dis[r] * ew[e] * g_dis[c];   // L_hat weight (sym norm, lambda_max=2)
    }
}

// ---------------- temporal conv 1 (register weights) -------------------------
// Warp = one (n,b) strip; lane = channels {2ln, 2ln+1}. Weights (36) + bias (6)
// in registers (9 coalesced LDG.128 + 3 LDG.64); X = 12 uniform LDG.64;
// outputs coalesced STG.64. No shared memory at all.
__global__ __launch_bounds__(256) void tconv1_kernel(const float* __restrict__ X,
        const float* __restrict__ w1, const float* __restrict__ b1,
        const float* __restrict__ w2, const float* __restrict__ b2,
        const float* __restrict__ w3, const float* __restrict__ b3) {
    int tid = threadIdx.x;
    int ln  = tid & 31;
    int gw  = blockIdx.x*8 + (tid >> 5);     // strip id s = n*8 + b, 0..79999
    int n = gw >> 3, b = gw & 7;

    // load weights: W[m][hh*6 + c*3 + k], hh in {0,1} for h = 2ln+hh
    float W[3][12];
#pragma unroll
    for (int m = 0; m < 3; m++) {
        const float* w = (m == 0) ? w1 : ((m == 1) ? w2 : w3);
        float4 a = *(const float4*)(w + 12*ln);
        float4 c = *(const float4*)(w + 12*ln + 4);
        float4 d = *(const float4*)(w + 12*ln + 8);
        W[m][0]=a.x; W[m][1]=a.y; W[m][2]=a.z;  W[m][3]=a.w;  W[m][4]=c.x;  W[m][5]=c.y;
        W[m][6]=c.z; W[m][7]=c.w; W[m][8]=d.x;  W[m][9]=d.y;  W[m][10]=d.z; W[m][11]=d.w;
    }
    float2 Bv[3];
    Bv[0] = *(const float2*)(b1 + 2*ln);
    Bv[1] = *(const float2*)(b2 + 2*ln);
    Bv[2] = *(const float2*)(b3 + 2*ln);

    // load X strip: xv[t] = (X[..c0], X[..c1]) for t = 0..11 (uniform per warp)
    float2 xv[TTI];
#pragma unroll
    for (int t = 0; t < TTI; t++)
        xv[t] = *(const float2*)(X + (b*TTI + t)*(NN*CIN) + n*CIN);

#pragma unroll
    for (int t = 0; t < TTI; t++) {
        float a00 = Bv[0].x, a01 = Bv[0].y;
        float a10 = Bv[1].x, a11 = Bv[1].y;
        float a20 = Bv[2].x, a21 = Bv[2].y;
#pragma unroll
        for (int k = 0; k < 3; k++) {
            int t2 = t + k - 1;
            if (t2 >= 0 && t2 < TTI) {
                float x0 = xv[t2].x, x1 = xv[t2].y;
                a00 += x0*W[0][k]   + x1*W[0][3+k];
                a01 += x0*W[0][6+k] + x1*W[0][9+k];
                a10 += x0*W[1][k]   + x1*W[1][3+k];
                a11 += x0*W[1][6+k] + x1*W[1][9+k];
                a20 += x0*W[2][k]   + x1*W[2][3+k];
                a21 += x0*W[2][6+k] + x1*W[2][9+k];
            }
        }
        float sg0 = 1.f/(1.f + expf(-a10));
        float sg1 = 1.f/(1.f + expf(-a11));
        float2 o;
        o.x = fmaxf(a00*sg0 + a20, 0.f);
        o.y = fmaxf(a01*sg1 + a21, 0.f);
        *(float2*)&g_T0[(gw*TTI + t)*HH + 2*ln] = o;
    }
}

// ---------------- graph prop: y[n,:] = sum_e w[e] * x[col[e],:] ----------------
__global__ __launch_bounds__(256) void prop_kernel(int mode) {
    const float4* __restrict__ x = (const float4*)(mode ? g_Y1 : g_T0);
    float4* __restrict__ y       = (float4*)(mode ? g_Y2 : g_Y1);
    int n = blockIdx.x;
    int f = blockIdx.y*256 + threadIdx.x;     // float4 index in [0,1536)
    int beg = g_rowptr[n], end = g_rowptr[n+1];
    float4 acc = make_float4(0.f, 0.f, 0.f, 0.f);
    int e = beg;
    for (; e + 4 <= end; e += 4) {
        int   c0 = g_colidx[e],   c1 = g_colidx[e+1], c2 = g_colidx[e+2], c3 = g_colidx[e+3];
        float w0 = g_ew[e],       w1 = g_ew[e+1],     w2 = g_ew[e+2],     w3 = g_ew[e+3];
        float4 v0 = x[c0*F4 + f], v1 = x[c1*F4 + f],  v2 = x[c2*F4 + f],  v3 = x[c3*F4 + f];
        acc.x += w0*v0.x + w1*v1.x + w2*v2.x + w3*v3.x;
        acc.y += w0*v0.y + w1*v1.y + w2*v2.y + w3*v3.y;
        acc.z += w0*v0.z + w1*v1.z + w2*v2.z + w3*v3.z;
        acc.w += w0*v0.w + w1*v1.w + w2*v2.w + w3*v3.w;
    }
    for (; e < end; e++) {
        int c = g_colidx[e]; float w = g_ew[e];
        float4 v = x[c*F4 + f];
        acc.x += w*v.x; acc.y += w*v.y; acc.z += w*v.z; acc.w += w*v.w;
    }
    y[n*F4 + f] = acc;
}

// ---------------- cheb combine: S = relu(T0@W0 + Y1@W1 + (2*Y2-T0)@W2 + b) ----
// 512 threads, 128 positions/block (16 warps x 8 pos/thread), 1 CTA/SM.
// xs transposed [m][i][p] stride 132, XOR chunk-swizzle (reads are broadcast).
#define CMB_WS_F  (3*64*64)          /* 12288 */
#define CMB_XS_ST 132
#define CMB_XS_MS (64*CMB_XS_ST)     /* 8448 per matrix */
#define CMB_XS_F  (3*CMB_XS_MS)      /* 25344 */
#define CMB_SMEM_BYTES ((CMB_WS_F + CMB_XS_F + 64)*4)
__device__ __forceinline__ int cmb_xaddr(int i, int p) {
    int pc = p >> 2, of = p & 3;
    return i*CMB_XS_ST + (((pc ^ ((i>>1)&7)) << 2) | of);
}
__global__ __launch_bounds__(512, 1) void combine_kernel(const float* __restrict__ Wc,
                                                         const float* __restrict__ bias) {
    extern __shared__ float sm[];
    float* Ws = sm;                         // [m*4096 + i*64 + h]
    float* xs = sm + CMB_WS_F;              // swizzled [m][i][p]
    float* bs = xs + CMB_XS_F;
    int tid = threadIdx.x;
    for (int idx = tid; idx < CMB_WS_F; idx += 512) Ws[idx] = Wc[idx];
    if (tid < 64) bs[tid] = bias[tid];
    int base = blockIdx.x * 128 * 64;       // 128 positions * 64 features
    {
        int wid = tid >> 5, lane = tid & 31;
        int i0 = 2*lane;
#pragma unroll
        for (int it = 0; it < 4; it++) {
            int pp = (wid + 16*it) * 2;     // even position
            int go0 = base + pp*64 + i0;
            int go1 = go0 + 64;
            float2 a0 = *(const float2*)&g_T0[go0], a1 = *(const float2*)&g_T0[go1];
            float2 u0 = *(const float2*)&g_Y1[go0], u1 = *(const float2*)&g_Y1[go1];
            float2 v0 = *(const float2*)&g_Y2[go0], v1 = *(const float2*)&g_Y2[go1];
            int ad0 = cmb_xaddr(i0, pp), ad1 = cmb_xaddr(i0+1, pp);
            *(float2*)&xs[ad0]                 = make_float2(a0.x, a1.x);
            *(float2*)&xs[ad1]                 = make_float2(a0.y, a1.y);
            *(float2*)&xs[CMB_XS_MS + ad0]     = make_float2(u0.x, u1.x);
            *(float2*)&xs[CMB_XS_MS + ad1]     = make_float2(u0.y, u1.y);
            *(float2*)&xs[2*CMB_XS_MS + ad0]   = make_float2(2.f*v0.x - a0.x, 2.f*v1.x - a1.x);
            *(float2*)&xs[2*CMB_XS_MS + ad1]   = make_float2(2.f*v0.y - a0.y, 2.f*v1.y - a1.y);
        }
    }
    __syncthreads();

    int og = tid & 31, pg = tid >> 5;
    int p0 = pg * 8;                        // 8 positions per thread (4 pairs)
    ull acc0[4], acc1[4];
    {
        ull b0 = pack2(bs[og], bs[og]);
        ull b1_ = pack2(bs[og+32], bs[og+32]);
#pragma unroll
        for (int j = 0; j < 4; j++) { acc0[j] = b0; acc1[j] = b1_; }
    }
    for (int i = 0; i < 64; i++) {
        float w0a = Ws[i*64+og],        w0b = Ws[i*64+og+32];
        float w1a = Ws[4096+i*64+og],   w1b = Ws[4096+i*64+og+32];
        float w2a = Ws[8192+i*64+og],   w2b = Ws[8192+i*64+og+32];
        ull W0a = pack2(w0a,w0a), W0b = pack2(w0b,w0b);
        ull W1a = pack2(w1a,w1a), W1b = pack2(w1b,w1b);
        ull W2a = pack2(w2a,w2a), W2b = pack2(w2b,w2b);
        int ax = cmb_xaddr(i, p0);          // 16B-aligned chunk; p0..p0+7 = 2 chunks
        int ax2 = cmb_xaddr(i, p0 + 4);
        ulonglong2 v0a = *(const ulonglong2*)(xs + ax);
        ulonglong2 v0b = *(const ulonglong2*)(xs + ax2);
        ulonglong2 v1a = *(const ulonglong2*)(xs + CMB_XS_MS + ax);
        ulonglong2 v1b = *(const ulonglong2*)(xs + CMB_XS_MS + ax2);
        ulonglong2 v2a = *(const ulonglong2*)(xs + 2*CMB_XS_MS + ax);
        ulonglong2 v2b = *(const ulonglong2*)(xs + 2*CMB_XS_MS + ax2);
        fma2(acc0[0], v0a.x, W0a); fma2(acc1[0], v0a.x, W0b);
        fma2(acc0[1], v0a.y, W0a); fma2(acc1[1], v0a.y, W0b);
        fma2(acc0[2], v0b.x, W0a); fma2(acc1[2], v0b.x, W0b);
        fma2(acc0[3], v0b.y, W0a); fma2(acc1[3], v0b.y, W0b);
        fma2(acc0[0], v1a.x, W1a); fma2(acc1[0], v1a.x, W1b);
        fma2(acc0[1], v1a.y, W1a); fma2(acc1[1], v1a.y, W1b);
        fma2(acc0[2], v1b.x, W1a); fma2(acc1[2], v1b.x, W1b);
        fma2(acc0[3], v1b.y, W1a); fma2(acc1[3], v1b.y, W1b);
        fma2(acc0[0], v2a.x, W2a); fma2(acc1[0], v2a.x, W2b);
        fma2(acc0[1], v2a.y, W2a); fma2(acc1[1], v2a.y, W2b);
        fma2(acc0[2], v2b.x, W2a); fma2(acc1[2], v2b.x, W2b);
        fma2(acc0[3], v2b.y, W2a); fma2(acc1[3], v2b.y, W2b);
    }
#pragma unroll
    for (int j = 0; j < 4; j++) {
        float v0, v1;
        unpack2(v0, v1, acc0[j]);
        g_S[base + (p0+2*j)*64 + og]        = fmaxf(v0, 0.f);
        g_S[base + (p0+2*j+1)*64 + og]      = fmaxf(v1, 0.f);
        unpack2(v0, v1, acc1[j]);
        g_S[base + (p0+2*j)*64 + og + 32]   = fmaxf(v0, 0.f);
        g_S[base + (p0+2*j+1)*64 + og + 32] = fmaxf(v1, 0.f);
    }
}

// ---------------- temporal conv 2: g_S[N,B,T,H] -> out[B,T,N,H] ---------------
// 512 threads, 8 nb-pairs/block, warp = (pair, out-half): thread = 1 out chan
// x 6 packed t-pairs x 3 matrices. Full 64-out weights once per block.
#define T2_NB    8
#define T2_W_MS  (192*65)            /* 12480 per matrix */
#define T2_W_F   (3*T2_W_MS)         /* 37440 */
#define T2_XT_ST 114
#define T2_XT_F  (64*T2_XT_ST)       /* 7296 */
#define T2_SMEM_BYTES ((T2_W_F + T2_XT_F + 192)*4)
__global__ __launch_bounds__(512, 1) void tconv2_kernel(
        const float* __restrict__ w1, const float* __restrict__ b1,
        const float* __restrict__ w2, const float* __restrict__ b2,
        const float* __restrict__ w3, const float* __restrict__ b3,
        float* __restrict__ out) {
    extern __shared__ float sm[];
    float* Wl = sm;                         // [m*12480 + j*65 + o], j = c*3+k
    float* xt = Wl + T2_W_F;                // [c*114 + pair*14 + tt]
    float* bs = xt + T2_XT_F;               // [m*64 + o]
    int tid = threadIdx.x;
    int nb0 = blockIdx.x * T2_NB;

    for (int idx = tid; idx < 3*64*192; idx += 512) {
        int m = idx / 12288; int r = idx - m*12288; int o = r / 192; int j = r - o*192;
        const float* w = (m == 0) ? w1 : ((m == 1) ? w2 : w3);
        Wl[m*T2_W_MS + j*65 + o] = w[r];
    }
    if (tid < 192) {
        int m = tid >> 6, o = tid & 63;
        const float* b = (m == 0) ? b1 : ((m == 1) ? b2 : b3);
        bs[tid] = b[o];
    }
    {
        int wid = tid >> 5, lane = tid & 31;
        int c0 = 2*lane;
#pragma unroll
        for (int it = 0; it < 6; it++) {
            int r = wid + 16*it;            // 0..95 = pair*12 + t
            int pair = r / 12, t = r - pair*12;
            float2 v = *(const float2*)&g_S[(nb0+pair)*768 + t*64 + c0];
            xt[c0*T2_XT_ST + pair*14 + t + 1]     = v.x;
            xt[(c0+1)*T2_XT_ST + pair*14 + t + 1] = v.y;
        }
        for (int idx = tid; idx < 64*16; idx += 512) {
            int c = idx >> 4, rr = idx & 15;
            int pair = rr >> 1, e = rr & 1;
            xt[c*T2_XT_ST + pair*14 + (e ? 13 : 0)] = 0.f;
        }
    }
    __syncthreads();

    int lane = tid & 31, wid = tid >> 5;
    int pair = wid >> 1;                    // warp owns (pair, out-half)
    int o = (wid & 1)*32 + lane;
    int pairoff = pair * 14;
    ull acc[3][6];
#pragma unroll
    for (int m = 0; m < 3; m++) {
        ull b0 = pack2(bs[m*64+o], bs[m*64+o]);
#pragma unroll
        for (int pr = 0; pr < 6; pr++) acc[m][pr] = b0;
    }
    for (int c = 0; c < 64; c++) {
        const float* xr = xt + c*T2_XT_ST + pairoff;
        ull L[7], M[6];
#pragma unroll
        for (int q = 0; q < 7; q++) L[q] = *(const ull*)(xr + 2*q);
#pragma unroll
        for (int pr = 0; pr < 6; pr++) {
            float alo, ahi, blo, bhi;
            unpack2(alo, ahi, L[pr]);
            unpack2(blo, bhi, L[pr+1]);
            M[pr] = pack2(ahi, blo);
        }
        int jb = (c*3)*65;
#pragma unroll
        for (int m = 0; m < 3; m++) {
            const float* wb = Wl + m*T2_W_MS + jb;
            float w0 = wb[o], w1_ = wb[65+o], w2_ = wb[130+o];
            ull W0 = pack2(w0,w0), W1 = pack2(w1_,w1_), W2 = pack2(w2_,w2_);
#pragma unroll
            for (int pr = 0; pr < 6; pr++) {
                fma2(acc[m][pr], L[pr],   W0);
                fma2(acc[m][pr], M[pr],   W1);
                fma2(acc[m][pr], L[pr+1], W2);
            }
        }
    }
    {
        int nb = nb0 + pair; int n = nb >> 3; int b = nb & 7;
#pragma unroll
        for (int pr = 0; pr < 6; pr++) {
            int t = 2*pr;
            int obase  = ((b*TTI + t)*NN + n)*64 + o;
            int obase2 = obase + NN*64;
            float Pl,Ph,Ql,Qh,Rl,Rh;
            unpack2(Pl, Ph, acc[0][pr]);
            unpack2(Ql, Qh, acc[1][pr]);
            unpack2(Rl, Rh, acc[2][pr]);
            out[obase]  = fmaxf(Pl/(1.f+expf(-Ql)) + Rl, 0.f);
            out[obase2] = fmaxf(Ph/(1.f+expf(-Qh)) + Rh, 0.f);
        }
    }
}

// zero the accumulated histograms for the NEXT call (globals are zero at load)
__global__ void cleanup_kernel() {
    int i = blockIdx.x*256 + threadIdx.x;
    if (i < NN) { g_degw[i] = 0.f; g_cnt[i] = 0; }
}

// ---------------- launch ----------------
extern "C" void kernel_launch(void* const* d_in, const int* in_sizes, int n_in,
                              void* d_out, int out_size) {
    const float* X    = (const float*)d_in[0];
    const int*   ei   = (const int*)  d_in[1];
    const float* ew   = (const float*)d_in[2];
    const float* t1w1 = (const float*)d_in[3];  const float* t1b1 = (const float*)d_in[4];
    const float* t1w2 = (const float*)d_in[5];  const float* t1b2 = (const float*)d_in[6];
    const float* t1w3 = (const float*)d_in[7];  const float* t1b3 = (const float*)d_in[8];
    const float* cW   = (const float*)d_in[9];  const float* cb   = (const float*)d_in[10];
    const float* t2w1 = (const float*)d_in[11]; const float* t2b1 = (const float*)d_in[12];
    const float* t2w2 = (const float*)d_in[13]; const float* t2b2 = (const float*)d_in[14];
    const float* t2w3 = (const float*)d_in[15]; const float* t2b3 = (const float*)d_in[16];
    float* out = (float*)d_out;
    const int* row = ei;
    const int* col = ei + NE;

    cudaFuncSetAttribute(combine_kernel, cudaFuncAttributeMaxDynamicSharedMemorySize,
                         CMB_SMEM_BYTES);
    cudaFuncSetAttribute(tconv2_kernel, cudaFuncAttributeMaxDynamicSharedMemorySize,
                         T2_SMEM_BYTES);

    hist_kernel   <<<(NE+255)/256, 256>>>(row, ew);                       // 0
    scan_kernel   <<<1, 1024>>>();                                        // 1
    scatter_kernel<<<(NE+255)/256, 256>>>(row, col, ew);                  // 2
    tconv1_kernel <<<NN*BB/8, 256>>>(X, t1w1,t1b1, t1w2,t1b2, t1w3,t1b3); // 3 (profiled)

    prop_kernel   <<<dim3(NN, 6), 256>>>(0);   // Y1 = L * T0
    prop_kernel   <<<dim3(NN, 6), 256>>>(1);   // Y2 = L * Y1

    combine_kernel<<<NBT/128, 512, CMB_SMEM_BYTES>>>(cW, cb);

    tconv2_kernel <<<NN*BB/T2_NB, 512, T2_SMEM_BYTES>>>(
        t2w1,t2b1, t2w2,t2b2, t2w3,t2b3, out);

    cleanup_kernel<<<(NN+255)/256, 256>>>();
}